// round 15
// baseline (speedup 1.0000x reference)
#include <cuda_runtime.h>
#include <cuda_fp16.h>
#include <mma.h>

using namespace nvcuda;

// ---------------------------------------------------------------------------
// GCN: 3x (GraphConv norm='both') with BN+ReLU between, log_softmax at end.
// N=100000 nodes, E=1.6M edges, D=128, C=40.
//
// Round-15 = R14 with prop_fp16 FUSED into the wmma gemm's A-stage:
//   each 256-thread gemm block gather-aggregates its own 64 rows (8 nodes
//   per warp, MLP-4 CSR loop, fp32 accum) straight into the smem A-tile,
//   then wmma + fp32 epilogue (din scale + bias + BN stats).
//   Deletes 2 prop launches and 2x (26MB write + 26MB read) buffer traffic.
// ---------------------------------------------------------------------------

#define NMAX 100096
#define EMAX 1600000
#define DD 128
#define CHUNKS 1024

__device__ float   g_bufA[(size_t)NMAX * DD];   // 40-wide t buffer (fp16)
__device__ float   g_bufB[(size_t)NMAX * DD];   // gemm fp32 output
__device__ __half2 g_half[(size_t)NMAX * 64];   // fp16 gather copy (prop input)
__device__ __half  g_halfW[2 * DD * DD];        // fp16 W1 | W2
__device__ float   g_dout_is[NMAX];
__device__ float   g_din_is[NMAX];
__device__ int     g_deg_out[NMAX];   // zero on entry (module init / prop40 tail)
__device__ int     g_deg_in[NMAX];    // zero on entry
__device__ int     g_row_off[NMAX + 1];
__device__ int     g_cursor[NMAX];
__device__ int     g_csr_src[EMAX];
__device__ int     g_chunk_sum[CHUNKS];
__device__ float   g_colsum1[DD];     // zero on entry; re-zeroed in prop40
__device__ float   g_colsq1[DD];
__device__ float   g_colsum2[DD];
__device__ float   g_colsq2[DD];

// packed f32x2 helpers (sm_100+: lowers to FFMA2 / 64-bit regs)
#define FMA_F32X2(d, a, b, c) \
    asm("fma.rn.f32x2 %0, %1, %2, %3;" \
        : "=l"(d) : "l"(a), "l"(b), "l"(c))
#define PACKF2(out, lo, hi) \
    asm("mov.b64 %0, {%1, %2};" \
        : "=l"(out) : "r"(__float_as_uint(lo)), "r"(__float_as_uint(hi)))
#define UNPACKF2(lo, hi, in) \
    do { unsigned int _ulo, _uhi; \
         asm("mov.b64 {%0, %1}, %2;" : "=r"(_ulo), "=r"(_uhi) : "l"(in)); \
         lo = __uint_as_float(_ulo); hi = __uint_as_float(_uhi); } while (0)

// ---------------------------------------------------------------------------
__global__ void deg_count_kernel(const int* __restrict__ src,
                                 const int* __restrict__ dst, int E) {
    int i = blockIdx.x * blockDim.x + threadIdx.x;
    if (i < E) {
        atomicAdd(&g_deg_out[src[i]], 1);
        atomicAdd(&g_deg_in[dst[i]], 1);
    }
}

// ---------------------------------------------------------------------------
// Parallel exclusive scan of deg_in -> row_off (3 phases, full-chip).
// ---------------------------------------------------------------------------
__global__ void __launch_bounds__(256) chunk_sum_kernel(int N, int chunk) {
    int w = blockIdx.x * 8 + (threadIdx.x >> 5);
    if (w >= CHUNKS) return;
    int lane = threadIdx.x & 31;
    int lo = w * chunk, hi = min(lo + chunk, N);
    int s = 0;
    for (int i = lo + lane; i < hi; i += 32) s += g_deg_in[i];
    #pragma unroll
    for (int off = 16; off; off >>= 1)
        s += __shfl_down_sync(0xffffffffu, s, off);
    if (lane == 0) g_chunk_sum[w] = s;
}

__global__ void __launch_bounds__(1024) scan_chunks_kernel(int N) {
    __shared__ int sdata[1024];
    int t = threadIdx.x;
    int v = g_chunk_sum[t];
    sdata[t] = v;
    __syncthreads();
    #pragma unroll
    for (int off = 1; off < 1024; off <<= 1) {
        int u = (t >= off) ? sdata[t - off] : 0;
        __syncthreads();
        sdata[t] += u;
        __syncthreads();
    }
    g_chunk_sum[t] = sdata[t] - v;          // exclusive prefix per chunk
    if (t == 1023) g_row_off[N] = sdata[1023];
}

// fill_off + deg_inv folded: writes row_off/cursor AND deg^-1/2 arrays.
__global__ void __launch_bounds__(256) fill_off_kernel(int N, int chunk) {
    int w = blockIdx.x * 8 + (threadIdx.x >> 5);
    if (w >= CHUNKS) return;
    int lane = threadIdx.x & 31;
    int lo = w * chunk, hi = min(lo + chunk, N);
    int run = g_chunk_sum[w];
    for (int base = lo; base < hi; base += 32) {
        int i = base + lane;
        int v = 0;
        if (i < hi) {
            v = __ldg(&g_deg_in[i]);
            int dov = __ldg(&g_deg_out[i]);
            g_din_is[i]  = rsqrtf(fmaxf((float)v, 1.f));
            g_dout_is[i] = rsqrtf(fmaxf((float)dov, 1.f));
        }
        int incl = v;
        #pragma unroll
        for (int off = 1; off < 32; off <<= 1) {
            int t = __shfl_up_sync(0xffffffffu, incl, off);
            if (lane >= off) incl += t;
        }
        if (i < hi) {
            int off_i = run + incl - v;
            g_row_off[i] = off_i;
            g_cursor[i]  = off_i;
        }
        run += __shfl_sync(0xffffffffu, incl, 31);
    }
}

// ---------------------------------------------------------------------------
// Fused launch: blocks [0, qgrid): layer-1 prep (x * dout -> fp16 rows);
// [qgrid, qgrid+egrid): CSR fill; [qgrid+egrid, +wgrid): W1|W2 fp32->fp16.
// ---------------------------------------------------------------------------
__global__ void __launch_bounds__(256) csrfill_prep_kernel(
    const int* __restrict__ src, const int* __restrict__ dst, int E,
    const float4* __restrict__ x, __half2* __restrict__ outh, int N, int qgrid,
    const float* __restrict__ W1, const float* __restrict__ W2)
{
    int b = (int)blockIdx.x;
    if (b < qgrid) {
        int i = b * 256 + threadIdx.x;
        if (i < N * 32) {
            int node = i >> 5;
            float4 v = __ldg(x + i);
            float sc = __ldg(&g_dout_is[node]);
            outh[i * 2 + 0] = __floats2half2_rn(v.x * sc, v.y * sc);
            outh[i * 2 + 1] = __floats2half2_rn(v.z * sc, v.w * sc);
        }
    } else if (b < qgrid + ((E + 255) >> 8)) {
        int i = (b - qgrid) * 256 + threadIdx.x;
        if (i < E) {
            int pos = atomicAdd(&g_cursor[dst[i]], 1);
            g_csr_src[pos] = src[i];
        }
    } else {
        int i = (b - qgrid - ((E + 255) >> 8)) * 256 + threadIdx.x;
        if (i < 2 * DD * DD) {
            float w = (i < DD * DD) ? __ldg(W1 + i) : __ldg(W2 + i - DD * DD);
            g_halfW[i] = __float2half_rn(w);
        }
    }
}

// ---------------------------------------------------------------------------
// Layer-2 prep with inline BN: per-block compute of the 128 BN coefficients
// (from colsum/colsq stats) into smem, then BN+ReLU+dout scale -> fp16 rows.
// ---------------------------------------------------------------------------
__global__ void __launch_bounds__(256) prep_bn_kernel(
    const float4* __restrict__ in, __half2* __restrict__ outh, int N,
    const float* __restrict__ colsum, const float* __restrict__ colsq,
    const float* __restrict__ g, const float* __restrict__ be, float invN)
{
    __shared__ float sA[128], sB[128];
    int tid = threadIdx.x;
    if (tid < 128) {
        float mu  = __ldg(colsum + tid) * invN;
        float var = fmaf(-mu, mu, __ldg(colsq + tid) * invN);
        float a   = __ldg(g + tid) * rsqrtf(var + 1e-5f);
        sA[tid] = a;
        sB[tid] = fmaf(-mu, a, __ldg(be + tid));
    }
    __syncthreads();

    int i = blockIdx.x * 256 + tid;
    if (i >= N * 32) return;
    int node = i >> 5;
    int q    = i & 31;
    float4 v = __ldg(in + i);
    float4 a = *(const float4*)(sA + q * 4);
    float4 b = *(const float4*)(sB + q * 4);
    v.x = fmaxf(fmaf(v.x, a.x, b.x), 0.f);
    v.y = fmaxf(fmaf(v.y, a.y, b.y), 0.f);
    v.z = fmaxf(fmaf(v.z, a.z, b.z), 0.f);
    v.w = fmaxf(fmaf(v.w, a.w, b.w), 0.f);
    float sc = __ldg(&g_dout_is[node]);
    outh[i * 2 + 0] = __floats2half2_rn(v.x * sc, v.y * sc);
    outh[i * 2 + 1] = __floats2half2_rn(v.z * sc, v.w * sc);
}

// ---------------------------------------------------------------------------
// FUSED prop + tensor-core GEMM:
// Each 256-thread block owns 64 output rows. Phase 1: each of the 8 warps
// gather-aggregates 8 nodes (CSR, fp16 rows, fp32 accum, MLP-4) directly
// into the smem A-tile as fp16. Phase 2: wmma 64x128x128 (fp16 -> f32).
// Epilogue: din scale + bias + BN column stats + fp32 store.
// ---------------------------------------------------------------------------
#define SMEMG (64 * 128 * 4 + 128 * 128 * 2 + 64 * 128 * 2 + 256 * 4)

__global__ void __launch_bounds__(256) gemm_fused_kernel(
    const uint2* __restrict__ inh, const __half* __restrict__ Wh,
    const float* __restrict__ bias, float* __restrict__ out, int N,
    float* __restrict__ colsum, float* __restrict__ colsq)
{
    extern __shared__ float sm[];
    float*  sOut = sm;                              // 64*128 f32 (32KB)
    __half* sW   = (__half*)(sm + 64 * 128);        // 128*128 half (32KB)
    __half* sA   = sW + 128 * 128;                  // 64*128 half (16KB)
    float*  sSum = (float*)(sA + 64 * 128);         // [128]
    float*  sSq  = sSum + 128;                      // [128]
    int tid  = threadIdx.x;
    int row0 = blockIdx.x * 64;
    int w    = tid >> 5;
    int lane = tid & 31;

    if (tid < 128) { sSum[tid] = 0.f; sSq[tid] = 0.f; }

    // stage W (2048 uint4)
    {
        const uint4* W4 = (const uint4*)Wh;
        uint4* sW4 = (uint4*)sW;
        #pragma unroll
        for (int ii = 0; ii < 8; ii++)
            sW4[tid + ii * 256] = __ldg(W4 + tid + ii * 256);
    }

    // Phase 1: gather-aggregate 8 nodes per warp into the smem A-tile.
    // Lane l owns features [4l, 4l+4) of each row.
    for (int i = 0; i < 8; i++) {
        int r    = w * 8 + i;
        int node = row0 + r;
        float4 acc = make_float4(0.f, 0.f, 0.f, 0.f);
        if (node < N) {
            int start = __ldg(&g_row_off[node]);
            int end   = __ldg(&g_row_off[node + 1]);
            for (int base = start; base < end; base += 32) {
                int n = min(32, end - base);
                int s = 0;
                if (lane < n) s = __ldg(g_csr_src + base + lane);
                int j = 0;
                for (; j + 4 <= n; j += 4) {
                    int s0 = __shfl_sync(0xffffffffu, s, j);
                    int s1 = __shfl_sync(0xffffffffu, s, j + 1);
                    int s2 = __shfl_sync(0xffffffffu, s, j + 2);
                    int s3 = __shfl_sync(0xffffffffu, s, j + 3);
                    uint2 r0 = __ldg(inh + (size_t)s0 * 32 + lane);
                    uint2 r1 = __ldg(inh + (size_t)s1 * 32 + lane);
                    uint2 r2 = __ldg(inh + (size_t)s2 * 32 + lane);
                    uint2 r3 = __ldg(inh + (size_t)s3 * 32 + lane);
                    float2 a0 = __half22float2(*(const __half2*)&r0.x);
                    float2 b0 = __half22float2(*(const __half2*)&r0.y);
                    float2 a1 = __half22float2(*(const __half2*)&r1.x);
                    float2 b1 = __half22float2(*(const __half2*)&r1.y);
                    float2 a2 = __half22float2(*(const __half2*)&r2.x);
                    float2 b2 = __half22float2(*(const __half2*)&r2.y);
                    float2 a3 = __half22float2(*(const __half2*)&r3.x);
                    float2 b3 = __half22float2(*(const __half2*)&r3.y);
                    acc.x += (a0.x + a1.x) + (a2.x + a3.x);
                    acc.y += (a0.y + a1.y) + (a2.y + a3.y);
                    acc.z += (b0.x + b1.x) + (b2.x + b3.x);
                    acc.w += (b0.y + b1.y) + (b2.y + b3.y);
                }
                for (; j < n; j++) {
                    int sj = __shfl_sync(0xffffffffu, s, j);
                    uint2 rr = __ldg(inh + (size_t)sj * 32 + lane);
                    float2 a = __half22float2(*(const __half2*)&rr.x);
                    float2 b = __half22float2(*(const __half2*)&rr.y);
                    acc.x += a.x; acc.y += a.y; acc.z += b.x; acc.w += b.y;
                }
            }
        }
        __half2* ap = (__half2*)(sA + r * 128 + lane * 4);
        ap[0] = __floats2half2_rn(acc.x, acc.y);
        ap[1] = __floats2half2_rn(acc.z, acc.w);
    }
    __syncthreads();

    // Phase 2: wmma. warp w: rows m0 = (w&3)*16, cols n0 = (w>>2)*64
    int m0 = (w & 3) * 16;
    int n0 = (w >> 2) * 64;

    wmma::fragment<wmma::accumulator, 16, 16, 16, float> c[4];
    #pragma unroll
    for (int j = 0; j < 4; j++) wmma::fill_fragment(c[j], 0.f);

    #pragma unroll
    for (int k = 0; k < 128; k += 16) {
        wmma::fragment<wmma::matrix_a, 16, 16, 16, __half, wmma::row_major> a;
        wmma::load_matrix_sync(a, sA + m0 * 128 + k, 128);
        #pragma unroll
        for (int j = 0; j < 4; j++) {
            wmma::fragment<wmma::matrix_b, 16, 16, 16, __half, wmma::row_major> b;
            wmma::load_matrix_sync(b, sW + k * 128 + n0 + j * 16, 128);
            wmma::mma_sync(c[j], a, b, c[j]);
        }
    }
    #pragma unroll
    for (int j = 0; j < 4; j++)
        wmma::store_matrix_sync(sOut + m0 * 128 + n0 + j * 16, c[j], 128,
                                wmma::mem_row_major);
    __syncthreads();

    // epilogue: din scale + bias + BN stats + fp32 store
    float csum[4] = {0.f, 0.f, 0.f, 0.f};
    float csq[4]  = {0.f, 0.f, 0.f, 0.f};
    int cq = tid & 31;                 // float4 col group (fixed per thread)
    float4 bv = __ldg((const float4*)bias + cq);
    #pragma unroll
    for (int ii = 0; ii < 8; ii++) {
        int r  = (tid >> 5) + ii * 8;  // 8 rows per thread, stride 8
        int rr = row0 + r;
        if (rr < N) {
            float4 v = *((const float4*)(sOut + r * 128) + cq);
            float sc = __ldg(&g_din_is[rr]);
            float4 o;
            o.x = fmaf(v.x, sc, bv.x);
            o.y = fmaf(v.y, sc, bv.y);
            o.z = fmaf(v.z, sc, bv.z);
            o.w = fmaf(v.w, sc, bv.w);
            csum[0] += o.x; csq[0] = fmaf(o.x, o.x, csq[0]);
            csum[1] += o.y; csq[1] = fmaf(o.y, o.y, csq[1]);
            csum[2] += o.z; csq[2] = fmaf(o.z, o.z, csq[2]);
            csum[3] += o.w; csq[3] = fmaf(o.w, o.w, csq[3]);
            *((float4*)(out + (size_t)rr * 128) + cq) = o;
        }
    }
    #pragma unroll
    for (int j = 0; j < 4; j++) {
        atomicAdd(&sSum[cq * 4 + j], csum[j]);
        atomicAdd(&sSq[cq * 4 + j],  csq[j]);
    }
    __syncthreads();
    if (tid < 128) {
        atomicAdd(&colsum[tid], sSum[tid]);
        atomicAdd(&colsq[tid],  sSq[tid]);
    }
}

// ---------------------------------------------------------------------------
// Layer-3 pre-prop GEMM: t[r, 0..39] = dout_is[r] * (relu(bn(A[r,:])) @ W3).
// BN coefficients computed per-block in smem from layer-2 stats. fp16 t out.
// ---------------------------------------------------------------------------
#define SMEM40 ((128 * 64 + 128 * 68) * 4)

__global__ void __launch_bounds__(256) gemm40pre_kernel(
    const float* __restrict__ A, const float* __restrict__ W3,
    __half2* __restrict__ t, int N,
    const float* __restrict__ colsum, const float* __restrict__ colsq,
    const float* __restrict__ g, const float* __restrict__ be, float invN)
{
    extern __shared__ float sm[];
    float* sW   = sm;                       // [k][c] padded to 64 cols
    float* sAT  = sm + 128 * 64;            // [k][r] ld 68
    __shared__ float sA[128], sB[128];
    int tid  = threadIdx.x;
    int row0 = blockIdx.x * 64;

    if (tid < 128) {
        float mu  = __ldg(colsum + tid) * invN;
        float var = fmaf(-mu, mu, __ldg(colsq + tid) * invN);
        float a   = __ldg(g + tid) * rsqrtf(var + 1e-5f);
        sA[tid] = a;
        sB[tid] = fmaf(-mu, a, __ldg(be + tid));
    }
    for (int i = tid; i < 128 * 64; i += 256) sW[i] = 0.f;
    __syncthreads();
    for (int i = tid; i < 128 * 40; i += 256) {
        int k = i / 40, c = i - k * 40;
        sW[k * 64 + c] = __ldg(W3 + i);
    }
    #pragma unroll
    for (int ii = 0; ii < 8; ii++) {
        int i  = tid + ii * 256;
        int r  = i >> 5;
        int k4 = (i & 31) << 2;
        int rr = row0 + r;
        float4 v = make_float4(0.f, 0.f, 0.f, 0.f);
        if (rr < N) v = __ldg((const float4*)(A + (size_t)rr * 128 + k4));
        float4 a = *(const float4*)(sA + k4);
        float4 b = *(const float4*)(sB + k4);
        sAT[(k4 + 0) * 68 + r] = fmaxf(fmaf(v.x, a.x, b.x), 0.f);
        sAT[(k4 + 1) * 68 + r] = fmaxf(fmaf(v.y, a.y, b.y), 0.f);
        sAT[(k4 + 2) * 68 + r] = fmaxf(fmaf(v.z, a.z, b.z), 0.f);
        sAT[(k4 + 3) * 68 + r] = fmaxf(fmaf(v.w, a.w, b.w), 0.f);
    }
    __syncthreads();

    int cg = (tid & 15) << 2;   // cols [cg, cg+4) of 64 (only <40 real)
    int rg = (tid >> 4) << 2;   // rows [rg, rg+4)

    unsigned long long accp[2][4];   // row pairs (rg,rg+1),(rg+2,rg+3)
    #pragma unroll
    for (int pr = 0; pr < 2; pr++)
        #pragma unroll
        for (int j = 0; j < 4; j++) accp[pr][j] = 0ull;

    #pragma unroll 8
    for (int k = 0; k < 128; k++) {
        float4 wv = *(const float4*)(sW + k * 64 + cg);
        ulonglong2 a01 = *(const ulonglong2*)(sAT + k * 68 + rg);
        unsigned long long ap[2] = {a01.x, a01.y};
        unsigned long long wd[4];
        PACKF2(wd[0], wv.x, wv.x);
        PACKF2(wd[1], wv.y, wv.y);
        PACKF2(wd[2], wv.z, wv.z);
        PACKF2(wd[3], wv.w, wv.w);
        #pragma unroll
        for (int pr = 0; pr < 2; pr++)
            #pragma unroll
            for (int j = 0; j < 4; j++)
                FMA_F32X2(accp[pr][j], ap[pr], wd[j], accp[pr][j]);
    }

    float acc[4][4];
    #pragma unroll
    for (int pr = 0; pr < 2; pr++)
        #pragma unroll
        for (int j = 0; j < 4; j++) {
            float lo, hi;
            UNPACKF2(lo, hi, accp[pr][j]);
            acc[2 * pr + 0][j] = lo;
            acc[2 * pr + 1][j] = hi;
        }

    if (cg < 40) {
        #pragma unroll
        for (int i = 0; i < 4; i++) {
            int rr = row0 + rg + i;
            if (rr < N) {
                float sc = __ldg(&g_dout_is[rr]);
                __half2* tp = t + (size_t)rr * 20 + (cg >> 1);
                tp[0] = __floats2half2_rn(acc[i][0] * sc, acc[i][1] * sc);
                tp[1] = __floats2half2_rn(acc[i][2] * sc, acc[i][3] * sc);
            }
        }
    }
}

// ---------------------------------------------------------------------------
// 40-wide fp16 CSR propagation + bias + log_softmax. One warp per dst node.
// Lanes 0..9 own 4 features each (uint2 = 2x half2). fp32 accumulation.
// Tail duty: re-zero scratch (deg counters + BN stats) for the next call.
// ---------------------------------------------------------------------------
__global__ void __launch_bounds__(256) prop40_kernel(
    const uint2* __restrict__ t, const float* __restrict__ b3,
    float* __restrict__ out, int N)
{
    int gid = blockIdx.x * 256 + threadIdx.x;
    if (gid < N) { g_deg_out[gid] = 0; g_deg_in[gid] = 0; }
    if (gid < 128) {
        g_colsum1[gid] = 0.f; g_colsq1[gid] = 0.f;
        g_colsum2[gid] = 0.f; g_colsq2[gid] = 0.f;
    }

    int node = blockIdx.x * 8 + (threadIdx.x >> 5);
    if (node >= N) return;
    int lane = threadIdx.x & 31;
    bool act = lane < 10;
    int start = __ldg(&g_row_off[node]);
    int end   = __ldg(&g_row_off[node + 1]);

    float4 acc = make_float4(0.f, 0.f, 0.f, 0.f);
    for (int base = start; base < end; base += 32) {
        int n = min(32, end - base);
        int s = 0;
        if (lane < n) s = __ldg(g_csr_src + base + lane);
        int j = 0;
        for (; j + 4 <= n; j += 4) {
            int s0 = __shfl_sync(0xffffffffu, s, j);
            int s1 = __shfl_sync(0xffffffffu, s, j + 1);
            int s2 = __shfl_sync(0xffffffffu, s, j + 2);
            int s3 = __shfl_sync(0xffffffffu, s, j + 3);
            if (act) {
                uint2 r0 = __ldg(t + (size_t)s0 * 10 + lane);
                uint2 r1 = __ldg(t + (size_t)s1 * 10 + lane);
                uint2 r2 = __ldg(t + (size_t)s2 * 10 + lane);
                uint2 r3 = __ldg(t + (size_t)s3 * 10 + lane);
                float2 a0 = __half22float2(*(const __half2*)&r0.x);
                float2 b0 = __half22float2(*(const __half2*)&r0.y);
                float2 a1 = __half22float2(*(const __half2*)&r1.x);
                float2 b1 = __half22float2(*(const __half2*)&r1.y);
                float2 a2 = __half22float2(*(const __half2*)&r2.x);
                float2 b2 = __half22float2(*(const __half2*)&r2.y);
                float2 a3 = __half22float2(*(const __half2*)&r3.x);
                float2 b3 = __half22float2(*(const __half2*)&r3.y);
                acc.x += (a0.x + a1.x) + (a2.x + a3.x);
                acc.y += (a0.y + a1.y) + (a2.y + a3.y);
                acc.z += (b0.x + b1.x) + (b2.x + b3.x);
                acc.w += (b0.y + b1.y) + (b2.y + b3.y);
            }
        }
        for (; j < n; j++) {
            int sj = __shfl_sync(0xffffffffu, s, j);
            if (act) {
                uint2 r = __ldg(t + (size_t)sj * 10 + lane);
                float2 a = __half22float2(*(const __half2*)&r.x);
                float2 b = __half22float2(*(const __half2*)&r.y);
                acc.x += a.x; acc.y += a.y; acc.z += b.x; acc.w += b.y;
            }
        }
    }

    float din = __ldg(&g_din_is[node]);
    float4 o = make_float4(0.f, 0.f, 0.f, 0.f);
    if (act) {
        float4 bv = __ldg(((const float4*)b3) + lane);
        o.x = fmaf(acc.x, din, bv.x);
        o.y = fmaf(acc.y, din, bv.y);
        o.z = fmaf(acc.z, din, bv.z);
        o.w = fmaf(acc.w, din, bv.w);
    }
    float m = act ? fmaxf(fmaxf(o.x, o.y), fmaxf(o.z, o.w)) : -1e30f;
    #pragma unroll
    for (int off = 16; off; off >>= 1)
        m = fmaxf(m, __shfl_xor_sync(0xffffffffu, m, off));
    float e = act ? (expf(o.x - m) + expf(o.y - m) +
                     expf(o.z - m) + expf(o.w - m)) : 0.f;
    #pragma unroll
    for (int off = 16; off; off >>= 1)
        e += __shfl_xor_sync(0xffffffffu, e, off);
    float lse = m + logf(e);
    if (act) {
        float4 r;
        r.x = o.x - lse; r.y = o.y - lse; r.z = o.z - lse; r.w = o.w - lse;
        *(float4*)(out + (size_t)node * 40 + lane * 4) = r;
    }
}

// ---------------------------------------------------------------------------
extern "C" void kernel_launch(void* const* d_in, const int* in_sizes, int n_in,
                              void* d_out, int out_size)
{
    const float* x   = (const float*)d_in[0];
    const int*   src = (const int*)d_in[1];
    const int*   dst = (const int*)d_in[2];
    const float* W1  = (const float*)d_in[3];
    const float* b1  = (const float*)d_in[4];
    const float* g1  = (const float*)d_in[5];
    const float* be1 = (const float*)d_in[6];
    const float* W2  = (const float*)d_in[7];
    const float* b2  = (const float*)d_in[8];
    const float* g2  = (const float*)d_in[9];
    const float* be2 = (const float*)d_in[10];
    const float* W3  = (const float*)d_in[11];
    const float* b3  = (const float*)d_in[12];

    int N = in_sizes[0] / DD;
    int E = in_sizes[1];
    float* out = (float*)d_out;

    float *bufA, *bufB, *cs1, *cq1, *cs2, *cq2;
    __half2 *bufH;
    __half  *bufW;
    cudaGetSymbolAddress((void**)&bufA, g_bufA);
    cudaGetSymbolAddress((void**)&bufB, g_bufB);
    cudaGetSymbolAddress((void**)&bufH, g_half);
    cudaGetSymbolAddress((void**)&bufW, g_halfW);
    cudaGetSymbolAddress((void**)&cs1, g_colsum1);
    cudaGetSymbolAddress((void**)&cq1, g_colsq1);
    cudaGetSymbolAddress((void**)&cs2, g_colsum2);
    cudaGetSymbolAddress((void**)&cq2, g_colsq2);

    cudaFuncSetAttribute(gemm_fused_kernel,
                         cudaFuncAttributeMaxDynamicSharedMemorySize, SMEMG);
    cudaFuncSetAttribute(gemm40pre_kernel,
                         cudaFuncAttributeMaxDynamicSharedMemorySize, SMEM40);

    int egrid  = (E + 255) / 256;
    int pgrid  = (N + 7) / 8;          // 8 warps (nodes) per 256-thread block
    int qgrid  = (N * 32 + 255) / 256; // prep: one thread per float4
    int wgrid  = (2 * DD * DD + 255) / 256;  // W fp16 conversion blocks
    int ggrid  = (N + 63) / 64;
    int chunk  = (N + CHUNKS - 1) / CHUNKS;
    float invN = 1.0f / (float)N;

    // 1-4: degrees + CSR offsets (deg arrays arrive zeroed)
    deg_count_kernel<<<egrid, 256>>>(src, dst, E);
    chunk_sum_kernel<<<CHUNKS / 8, 256>>>(N, chunk);
    scan_chunks_kernel<<<1, 1024>>>(N);
    fill_off_kernel<<<CHUNKS / 8, 256>>>(N, chunk);

    // 5: CSR fill + layer-1 prep + W1/W2 fp16 conversion (one launch)
    csrfill_prep_kernel<<<qgrid + egrid + wgrid, 256>>>(
        src, dst, E, (const float4*)x, bufH, N, qgrid, W1, W2);

    // 6: layer 1 (prop fused into gemm A-stage)
    gemm_fused_kernel<<<ggrid, 256, SMEMG>>>(
        (const uint2*)bufH, bufW, b1, bufB, N, cs1, cq1);

    // 7-8: layer 2
    prep_bn_kernel<<<qgrid, 256>>>((const float4*)bufB, bufH, N,
                                   cs1, cq1, g1, be1, invN);
    gemm_fused_kernel<<<ggrid, 256, SMEMG>>>(
        (const uint2*)bufH, bufW + DD * DD, b2, bufB, N, cs2, cq2);

    // 9-10: layer 3 (GEMM first — prop and @W3 commute), then 40-wide prop
    gemm40pre_kernel<<<ggrid, 256, SMEM40>>>(bufB, W3, (__half2*)bufA, N,
                                             cs2, cq2, g2, be2, invN);
    prop40_kernel<<<pgrid, 256>>>((const uint2*)bufA, b3, out, N);
}

// round 16
// speedup vs baseline: 1.2066x; 1.2066x over previous
#include <cuda_runtime.h>
#include <cuda_fp16.h>
#include <mma.h>

using namespace nvcuda;

// ---------------------------------------------------------------------------
// GCN: 3x (GraphConv norm='both') with BN+ReLU between, log_softmax at end.
// N=100000 nodes, E=1.6M edges, D=128, C=40.
//
// Round-16 = R14 (best-shape pipeline: standalone high-occupancy props +
// wmma gemms) with bufB stored as fp16 (halves 4x 51MB-class buffer trips:
// gemm writes, prep_bn read, gemm40pre read). BN stats remain fp32-exact.
// R15's prop-into-gemm fusion reverted (killed gather occupancy, +93us).
// ---------------------------------------------------------------------------

#define NMAX 100096
#define EMAX 1600000
#define DD 128
#define CHUNKS 1024

__device__ float   g_bufA[(size_t)NMAX * DD];   // 40-wide t buffer (fp16)
__device__ __half2 g_bufB[(size_t)NMAX * 64];   // gemm fp16 output
__device__ __half2 g_half[(size_t)NMAX * 64];   // fp16 gather copy (prop input)
__device__ __half2 g_halfA[(size_t)NMAX * 64];  // fp16 prop output (gemm A)
__device__ __half  g_halfW[2 * DD * DD];        // fp16 W1 | W2
__device__ float   g_dout_is[NMAX];
__device__ float   g_din_is[NMAX];
__device__ int     g_deg_out[NMAX];   // zero on entry (module init / prop40 tail)
__device__ int     g_deg_in[NMAX];    // zero on entry
__device__ int     g_row_off[NMAX + 1];
__device__ int     g_cursor[NMAX];
__device__ int     g_csr_src[EMAX];
__device__ int     g_chunk_sum[CHUNKS];
__device__ float   g_colsum1[DD];     // zero on entry; re-zeroed in prop40
__device__ float   g_colsq1[DD];
__device__ float   g_colsum2[DD];
__device__ float   g_colsq2[DD];

// packed f32x2 helpers (sm_100+: lowers to FFMA2 / 64-bit regs)
#define FMA_F32X2(d, a, b, c) \
    asm("fma.rn.f32x2 %0, %1, %2, %3;" \
        : "=l"(d) : "l"(a), "l"(b), "l"(c))
#define PACKF2(out, lo, hi) \
    asm("mov.b64 %0, {%1, %2};" \
        : "=l"(out) : "r"(__float_as_uint(lo)), "r"(__float_as_uint(hi)))
#define UNPACKF2(lo, hi, in) \
    do { unsigned int _ulo, _uhi; \
         asm("mov.b64 {%0, %1}, %2;" : "=r"(_ulo), "=r"(_uhi) : "l"(in)); \
         lo = __uint_as_float(_ulo); hi = __uint_as_float(_uhi); } while (0)

// ---------------------------------------------------------------------------
__global__ void deg_count_kernel(const int* __restrict__ src,
                                 const int* __restrict__ dst, int E) {
    int i = blockIdx.x * blockDim.x + threadIdx.x;
    if (i < E) {
        atomicAdd(&g_deg_out[src[i]], 1);
        atomicAdd(&g_deg_in[dst[i]], 1);
    }
}

// ---------------------------------------------------------------------------
// Parallel exclusive scan of deg_in -> row_off (3 phases, full-chip).
// ---------------------------------------------------------------------------
__global__ void __launch_bounds__(256) chunk_sum_kernel(int N, int chunk) {
    int w = blockIdx.x * 8 + (threadIdx.x >> 5);
    if (w >= CHUNKS) return;
    int lane = threadIdx.x & 31;
    int lo = w * chunk, hi = min(lo + chunk, N);
    int s = 0;
    for (int i = lo + lane; i < hi; i += 32) s += g_deg_in[i];
    #pragma unroll
    for (int off = 16; off; off >>= 1)
        s += __shfl_down_sync(0xffffffffu, s, off);
    if (lane == 0) g_chunk_sum[w] = s;
}

__global__ void __launch_bounds__(1024) scan_chunks_kernel(int N) {
    __shared__ int sdata[1024];
    int t = threadIdx.x;
    int v = g_chunk_sum[t];
    sdata[t] = v;
    __syncthreads();
    #pragma unroll
    for (int off = 1; off < 1024; off <<= 1) {
        int u = (t >= off) ? sdata[t - off] : 0;
        __syncthreads();
        sdata[t] += u;
        __syncthreads();
    }
    g_chunk_sum[t] = sdata[t] - v;          // exclusive prefix per chunk
    if (t == 1023) g_row_off[N] = sdata[1023];
}

// fill_off + deg_inv folded: writes row_off/cursor AND deg^-1/2 arrays.
__global__ void __launch_bounds__(256) fill_off_kernel(int N, int chunk) {
    int w = blockIdx.x * 8 + (threadIdx.x >> 5);
    if (w >= CHUNKS) return;
    int lane = threadIdx.x & 31;
    int lo = w * chunk, hi = min(lo + chunk, N);
    int run = g_chunk_sum[w];
    for (int base = lo; base < hi; base += 32) {
        int i = base + lane;
        int v = 0;
        if (i < hi) {
            v = __ldg(&g_deg_in[i]);
            int dov = __ldg(&g_deg_out[i]);
            g_din_is[i]  = rsqrtf(fmaxf((float)v, 1.f));
            g_dout_is[i] = rsqrtf(fmaxf((float)dov, 1.f));
        }
        int incl = v;
        #pragma unroll
        for (int off = 1; off < 32; off <<= 1) {
            int t = __shfl_up_sync(0xffffffffu, incl, off);
            if (lane >= off) incl += t;
        }
        if (i < hi) {
            int off_i = run + incl - v;
            g_row_off[i] = off_i;
            g_cursor[i]  = off_i;
        }
        run += __shfl_sync(0xffffffffu, incl, 31);
    }
}

// ---------------------------------------------------------------------------
// Fused launch: blocks [0, qgrid): layer-1 prep (x * dout -> fp16 rows);
// [qgrid, qgrid+egrid): CSR fill; [qgrid+egrid, +wgrid): W1|W2 fp32->fp16.
// ---------------------------------------------------------------------------
__global__ void __launch_bounds__(256) csrfill_prep_kernel(
    const int* __restrict__ src, const int* __restrict__ dst, int E,
    const float4* __restrict__ x, __half2* __restrict__ outh, int N, int qgrid,
    const float* __restrict__ W1, const float* __restrict__ W2)
{
    int b = (int)blockIdx.x;
    if (b < qgrid) {
        int i = b * 256 + threadIdx.x;
        if (i < N * 32) {
            int node = i >> 5;
            float4 v = __ldg(x + i);
            float sc = __ldg(&g_dout_is[node]);
            outh[i * 2 + 0] = __floats2half2_rn(v.x * sc, v.y * sc);
            outh[i * 2 + 1] = __floats2half2_rn(v.z * sc, v.w * sc);
        }
    } else if (b < qgrid + ((E + 255) >> 8)) {
        int i = (b - qgrid) * 256 + threadIdx.x;
        if (i < E) {
            int pos = atomicAdd(&g_cursor[dst[i]], 1);
            g_csr_src[pos] = src[i];
        }
    } else {
        int i = (b - qgrid - ((E + 255) >> 8)) * 256 + threadIdx.x;
        if (i < 2 * DD * DD) {
            float w = (i < DD * DD) ? __ldg(W1 + i) : __ldg(W2 + i - DD * DD);
            g_halfW[i] = __float2half_rn(w);
        }
    }
}

// ---------------------------------------------------------------------------
// Layer-2 prep with inline BN: per-block compute of the 128 BN coefficients
// (from colsum/colsq stats) into smem, then BN+ReLU+dout scale -> fp16 rows.
// Input is the fp16 gemm output (bufB).
// ---------------------------------------------------------------------------
__global__ void __launch_bounds__(256) prep_bn_kernel(
    const uint2* __restrict__ inh, __half2* __restrict__ outh, int N,
    const float* __restrict__ colsum, const float* __restrict__ colsq,
    const float* __restrict__ g, const float* __restrict__ be, float invN)
{
    __shared__ float sA[128], sB[128];
    int tid = threadIdx.x;
    if (tid < 128) {
        float mu  = __ldg(colsum + tid) * invN;
        float var = fmaf(-mu, mu, __ldg(colsq + tid) * invN);
        float a   = __ldg(g + tid) * rsqrtf(var + 1e-5f);
        sA[tid] = a;
        sB[tid] = fmaf(-mu, a, __ldg(be + tid));
    }
    __syncthreads();

    int i = blockIdx.x * 256 + tid;
    if (i >= N * 32) return;
    int node = i >> 5;
    int q    = i & 31;
    uint2 hv = __ldg(inh + i);
    float2 v01 = __half22float2(*(const __half2*)&hv.x);
    float2 v23 = __half22float2(*(const __half2*)&hv.y);
    float4 a = *(const float4*)(sA + q * 4);
    float4 b = *(const float4*)(sB + q * 4);
    float ox = fmaxf(fmaf(v01.x, a.x, b.x), 0.f);
    float oy = fmaxf(fmaf(v01.y, a.y, b.y), 0.f);
    float oz = fmaxf(fmaf(v23.x, a.z, b.z), 0.f);
    float ow = fmaxf(fmaf(v23.y, a.w, b.w), 0.f);
    float sc = __ldg(&g_dout_is[node]);
    outh[i * 2 + 0] = __floats2half2_rn(ox * sc, oy * sc);
    outh[i * 2 + 1] = __floats2half2_rn(oz * sc, ow * sc);
}

// ---------------------------------------------------------------------------
// fp16 CSR propagation: one warp per dst node. Lane l owns features
// [4l, 4l+4). fp32 accumulation, MLP-4. Output written as fp16 (gemm A).
// ---------------------------------------------------------------------------
__global__ void __launch_bounds__(256) prop_fp16_kernel(
    const uint2* __restrict__ inh, __half2* __restrict__ outh, int N)
{
    int node = blockIdx.x * 8 + (threadIdx.x >> 5);
    if (node >= N) return;
    int lane = threadIdx.x & 31;
    int start = __ldg(&g_row_off[node]);
    int end   = __ldg(&g_row_off[node + 1]);

    float4 acc = make_float4(0.f, 0.f, 0.f, 0.f);
    for (int base = start; base < end; base += 32) {
        int n = min(32, end - base);
        int s = 0;
        if (lane < n) s = __ldg(g_csr_src + base + lane);
        int j = 0;
        for (; j + 4 <= n; j += 4) {
            int s0 = __shfl_sync(0xffffffffu, s, j);
            int s1 = __shfl_sync(0xffffffffu, s, j + 1);
            int s2 = __shfl_sync(0xffffffffu, s, j + 2);
            int s3 = __shfl_sync(0xffffffffu, s, j + 3);
            uint2 r0 = __ldg(inh + (size_t)s0 * 32 + lane);
            uint2 r1 = __ldg(inh + (size_t)s1 * 32 + lane);
            uint2 r2 = __ldg(inh + (size_t)s2 * 32 + lane);
            uint2 r3 = __ldg(inh + (size_t)s3 * 32 + lane);
            float2 a0 = __half22float2(*(const __half2*)&r0.x);
            float2 b0 = __half22float2(*(const __half2*)&r0.y);
            float2 a1 = __half22float2(*(const __half2*)&r1.x);
            float2 b1 = __half22float2(*(const __half2*)&r1.y);
            float2 a2 = __half22float2(*(const __half2*)&r2.x);
            float2 b2 = __half22float2(*(const __half2*)&r2.y);
            float2 a3 = __half22float2(*(const __half2*)&r3.x);
            float2 b3 = __half22float2(*(const __half2*)&r3.y);
            acc.x += (a0.x + a1.x) + (a2.x + a3.x);
            acc.y += (a0.y + a1.y) + (a2.y + a3.y);
            acc.z += (b0.x + b1.x) + (b2.x + b3.x);
            acc.w += (b0.y + b1.y) + (b2.y + b3.y);
        }
        for (; j < n; j++) {
            int sj = __shfl_sync(0xffffffffu, s, j);
            uint2 r = __ldg(inh + (size_t)sj * 32 + lane);
            float2 a = __half22float2(*(const __half2*)&r.x);
            float2 b = __half22float2(*(const __half2*)&r.y);
            acc.x += a.x; acc.y += a.y; acc.z += b.x; acc.w += b.y;
        }
    }
    outh[(size_t)node * 64 + lane * 2 + 0] = __floats2half2_rn(acc.x, acc.y);
    outh[(size_t)node * 64 + lane * 2 + 1] = __floats2half2_rn(acc.z, acc.w);
}

// ---------------------------------------------------------------------------
// Tensor-core GEMM (wmma fp16 -> f32 accum):
// out[r,c] = din_is[r] * (A[r,:] @ W[:,c]) + bias[c], with BN stats fused.
// Block: 64 rows x 128 cols, 8 warps, each warp 16x64 (4x wmma 16x16x16).
// A fp16 (prop output), W fp16 (preconverted). Output stored fp16 (bufB);
// BN stats computed on the fp32 values before rounding.
// ---------------------------------------------------------------------------
#define SMEM128 (64 * 128 * 4 + 128 * 128 * 2 + 64 * 128 * 2 + 256 * 4)

__global__ void __launch_bounds__(256) gemm128_mma_kernel(
    const __half* __restrict__ Ah, const __half* __restrict__ Wh,
    const float* __restrict__ bias, __half2* __restrict__ outh, int N,
    float* __restrict__ colsum, float* __restrict__ colsq)
{
    extern __shared__ float sm[];
    float*  sOut = sm;                              // 64*128 f32 (32KB)
    __half* sW   = (__half*)(sm + 64 * 128);        // 128*128 half (32KB)
    __half* sA   = sW + 128 * 128;                  // 64*128 half (16KB)
    float*  sSum = (float*)(sA + 64 * 128);         // [128]
    float*  sSq  = sSum + 128;                      // [128]
    int tid  = threadIdx.x;
    int row0 = blockIdx.x * 64;

    if (tid < 128) { sSum[tid] = 0.f; sSq[tid] = 0.f; }

    // stage W (2048 uint4) and A (1024 uint4, zero-padded past N)
    {
        const uint4* W4 = (const uint4*)Wh;
        uint4* sW4 = (uint4*)sW;
        #pragma unroll
        for (int ii = 0; ii < 8; ii++)
            sW4[tid + ii * 256] = __ldg(W4 + tid + ii * 256);
        uint4* sA4 = (uint4*)sA;
        #pragma unroll
        for (int ii = 0; ii < 4; ii++) {
            int i = tid + ii * 256;          // uint4 index; 16/row
            int r = i >> 4, q = i & 15;
            int rr = row0 + r;
            uint4 v = make_uint4(0u, 0u, 0u, 0u);
            if (rr < N) v = __ldg((const uint4*)(Ah + (size_t)rr * 128) + q);
            sA4[i] = v;
        }
    }
    __syncthreads();

    // warp w: rows m0 = (w&3)*16, cols n0 = (w>>2)*64
    int w  = tid >> 5;
    int m0 = (w & 3) * 16;
    int n0 = (w >> 2) * 64;

    wmma::fragment<wmma::accumulator, 16, 16, 16, float> c[4];
    #pragma unroll
    for (int j = 0; j < 4; j++) wmma::fill_fragment(c[j], 0.f);

    #pragma unroll
    for (int k = 0; k < 128; k += 16) {
        wmma::fragment<wmma::matrix_a, 16, 16, 16, __half, wmma::row_major> a;
        wmma::load_matrix_sync(a, sA + m0 * 128 + k, 128);
        #pragma unroll
        for (int j = 0; j < 4; j++) {
            wmma::fragment<wmma::matrix_b, 16, 16, 16, __half, wmma::row_major> b;
            wmma::load_matrix_sync(b, sW + k * 128 + n0 + j * 16, 128);
            wmma::mma_sync(c[j], a, b, c[j]);
        }
    }
    #pragma unroll
    for (int j = 0; j < 4; j++)
        wmma::store_matrix_sync(sOut + m0 * 128 + n0 + j * 16, c[j], 128,
                                wmma::mem_row_major);
    __syncthreads();

    // epilogue: din scale + bias + BN stats (fp32) + fp16 store
    float csum[4] = {0.f, 0.f, 0.f, 0.f};
    float csq[4]  = {0.f, 0.f, 0.f, 0.f};
    int cq = tid & 31;                 // float4 col group (fixed per thread)
    float4 bv = __ldg((const float4*)bias + cq);
    #pragma unroll
    for (int ii = 0; ii < 8; ii++) {
        int r  = (tid >> 5) + ii * 8;  // 8 rows per thread, stride 8
        int rr = row0 + r;
        if (rr < N) {
            float4 v = *((const float4*)(sOut + r * 128) + cq);
            float sc = __ldg(&g_din_is[rr]);
            float4 o;
            o.x = fmaf(v.x, sc, bv.x);
            o.y = fmaf(v.y, sc, bv.y);
            o.z = fmaf(v.z, sc, bv.z);
            o.w = fmaf(v.w, sc, bv.w);
            csum[0] += o.x; csq[0] = fmaf(o.x, o.x, csq[0]);
            csum[1] += o.y; csq[1] = fmaf(o.y, o.y, csq[1]);
            csum[2] += o.z; csq[2] = fmaf(o.z, o.z, csq[2]);
            csum[3] += o.w; csq[3] = fmaf(o.w, o.w, csq[3]);
            __half2* op = outh + (size_t)rr * 64 + cq * 2;
            op[0] = __floats2half2_rn(o.x, o.y);
            op[1] = __floats2half2_rn(o.z, o.w);
        }
    }
    #pragma unroll
    for (int j = 0; j < 4; j++) {
        atomicAdd(&sSum[cq * 4 + j], csum[j]);
        atomicAdd(&sSq[cq * 4 + j],  csq[j]);
    }
    __syncthreads();
    if (tid < 128) {
        atomicAdd(&colsum[tid], sSum[tid]);
        atomicAdd(&colsq[tid],  sSq[tid]);
    }
}

// ---------------------------------------------------------------------------
// Layer-3 pre-prop GEMM: t[r, 0..39] = dout_is[r] * (relu(bn(A[r,:])) @ W3).
// A is fp16 (bufB). BN coefficients per-block in smem. fp16 t output.
// ---------------------------------------------------------------------------
#define SMEM40 ((128 * 64 + 128 * 68) * 4)

__global__ void __launch_bounds__(256) gemm40pre_kernel(
    const uint2* __restrict__ Ah, const float* __restrict__ W3,
    __half2* __restrict__ t, int N,
    const float* __restrict__ colsum, const float* __restrict__ colsq,
    const float* __restrict__ g, const float* __restrict__ be, float invN)
{
    extern __shared__ float sm[];
    float* sW   = sm;                       // [k][c] padded to 64 cols
    float* sAT  = sm + 128 * 64;            // [k][r] ld 68
    __shared__ float sA[128], sB[128];
    int tid  = threadIdx.x;
    int row0 = blockIdx.x * 64;

    if (tid < 128) {
        float mu  = __ldg(colsum + tid) * invN;
        float var = fmaf(-mu, mu, __ldg(colsq + tid) * invN);
        float a   = __ldg(g + tid) * rsqrtf(var + 1e-5f);
        sA[tid] = a;
        sB[tid] = fmaf(-mu, a, __ldg(be + tid));
    }
    for (int i = tid; i < 128 * 64; i += 256) sW[i] = 0.f;
    __syncthreads();
    for (int i = tid; i < 128 * 40; i += 256) {
        int k = i / 40, c = i - k * 40;
        sW[k * 64 + c] = __ldg(W3 + i);
    }
    #pragma unroll
    for (int ii = 0; ii < 8; ii++) {
        int i  = tid + ii * 256;
        int r  = i >> 5;
        int k4 = (i & 31) << 2;
        int rr = row0 + r;
        float2 v01 = make_float2(0.f, 0.f), v23 = make_float2(0.f, 0.f);
        if (rr < N) {
            uint2 hv = __ldg(Ah + (size_t)rr * 32 + (k4 >> 2));
            v01 = __half22float2(*(const __half2*)&hv.x);
            v23 = __half22float2(*(const __half2*)&hv.y);
        }
        float4 a = *(const float4*)(sA + k4);
        float4 b = *(const float4*)(sB + k4);
        sAT[(k4 + 0) * 68 + r] = fmaxf(fmaf(v01.x, a.x, b.x), 0.f);
        sAT[(k4 + 1) * 68 + r] = fmaxf(fmaf(v01.y, a.y, b.y), 0.f);
        sAT[(k4 + 2) * 68 + r] = fmaxf(fmaf(v23.x, a.z, b.z), 0.f);
        sAT[(k4 + 3) * 68 + r] = fmaxf(fmaf(v23.y, a.w, b.w), 0.f);
    }
    __syncthreads();

    int cg = (tid & 15) << 2;   // cols [cg, cg+4) of 64 (only <40 real)
    int rg = (tid >> 4) << 2;   // rows [rg, rg+4)

    unsigned long long accp[2][4];   // row pairs (rg,rg+1),(rg+2,rg+3)
    #pragma unroll
    for (int pr = 0; pr < 2; pr++)
        #pragma unroll
        for (int j = 0; j < 4; j++) accp[pr][j] = 0ull;

    #pragma unroll 8
    for (int k = 0; k < 128; k++) {
        float4 wv = *(const float4*)(sW + k * 64 + cg);
        ulonglong2 a01 = *(const ulonglong2*)(sAT + k * 68 + rg);
        unsigned long long ap[2] = {a01.x, a01.y};
        unsigned long long wd[4];
        PACKF2(wd[0], wv.x, wv.x);
        PACKF2(wd[1], wv.y, wv.y);
        PACKF2(wd[2], wv.z, wv.z);
        PACKF2(wd[3], wv.w, wv.w);
        #pragma unroll
        for (int pr = 0; pr < 2; pr++)
            #pragma unroll
            for (int j = 0; j < 4; j++)
                FMA_F32X2(accp[pr][j], ap[pr], wd[j], accp[pr][j]);
    }

    float acc[4][4];
    #pragma unroll
    for (int pr = 0; pr < 2; pr++)
        #pragma unroll
        for (int j = 0; j < 4; j++) {
            float lo, hi;
            UNPACKF2(lo, hi, accp[pr][j]);
            acc[2 * pr + 0][j] = lo;
            acc[2 * pr + 1][j] = hi;
        }

    if (cg < 40) {
        #pragma unroll
        for (int i = 0; i < 4; i++) {
            int rr = row0 + rg + i;
            if (rr < N) {
                float sc = __ldg(&g_dout_is[rr]);
                __half2* tp = t + (size_t)rr * 20 + (cg >> 1);
                tp[0] = __floats2half2_rn(acc[i][0] * sc, acc[i][1] * sc);
                tp[1] = __floats2half2_rn(acc[i][2] * sc, acc[i][3] * sc);
            }
        }
    }
}

// ---------------------------------------------------------------------------
// 40-wide fp16 CSR propagation + bias + log_softmax. One warp per dst node.
// Lanes 0..9 own 4 features each (uint2 = 2x half2). fp32 accumulation.
// Tail duty: re-zero scratch (deg counters + BN stats) for the next call.
// ---------------------------------------------------------------------------
__global__ void __launch_bounds__(256) prop40_kernel(
    const uint2* __restrict__ t, const float* __restrict__ b3,
    float* __restrict__ out, int N)
{
    int gid = blockIdx.x * 256 + threadIdx.x;
    if (gid < N) { g_deg_out[gid] = 0; g_deg_in[gid] = 0; }
    if (gid < 128) {
        g_colsum1[gid] = 0.f; g_colsq1[gid] = 0.f;
        g_colsum2[gid] = 0.f; g_colsq2[gid] = 0.f;
    }

    int node = blockIdx.x * 8 + (threadIdx.x >> 5);
    if (node >= N) return;
    int lane = threadIdx.x & 31;
    bool act = lane < 10;
    int start = __ldg(&g_row_off[node]);
    int end   = __ldg(&g_row_off[node + 1]);

    float4 acc = make_float4(0.f, 0.f, 0.f, 0.f);
    for (int base = start; base < end; base += 32) {
        int n = min(32, end - base);
        int s = 0;
        if (lane < n) s = __ldg(g_csr_src + base + lane);
        int j = 0;
        for (; j + 4 <= n; j += 4) {
            int s0 = __shfl_sync(0xffffffffu, s, j);
            int s1 = __shfl_sync(0xffffffffu, s, j + 1);
            int s2 = __shfl_sync(0xffffffffu, s, j + 2);
            int s3 = __shfl_sync(0xffffffffu, s, j + 3);
            if (act) {
                uint2 r0 = __ldg(t + (size_t)s0 * 10 + lane);
                uint2 r1 = __ldg(t + (size_t)s1 * 10 + lane);
                uint2 r2 = __ldg(t + (size_t)s2 * 10 + lane);
                uint2 r3 = __ldg(t + (size_t)s3 * 10 + lane);
                float2 a0 = __half22float2(*(const __half2*)&r0.x);
                float2 b0 = __half22float2(*(const __half2*)&r0.y);
                float2 a1 = __half22float2(*(const __half2*)&r1.x);
                float2 b1 = __half22float2(*(const __half2*)&r1.y);
                float2 a2 = __half22float2(*(const __half2*)&r2.x);
                float2 b2 = __half22float2(*(const __half2*)&r2.y);
                float2 a3 = __half22float2(*(const __half2*)&r3.x);
                float2 b3 = __half22float2(*(const __half2*)&r3.y);
                acc.x += (a0.x + a1.x) + (a2.x + a3.x);
                acc.y += (a0.y + a1.y) + (a2.y + a3.y);
                acc.z += (b0.x + b1.x) + (b2.x + b3.x);
                acc.w += (b0.y + b1.y) + (b2.y + b3.y);
            }
        }
        for (; j < n; j++) {
            int sj = __shfl_sync(0xffffffffu, s, j);
            if (act) {
                uint2 r = __ldg(t + (size_t)sj * 10 + lane);
                float2 a = __half22float2(*(const __half2*)&r.x);
                float2 b = __half22float2(*(const __half2*)&r.y);
                acc.x += a.x; acc.y += a.y; acc.z += b.x; acc.w += b.y;
            }
        }
    }

    float din = __ldg(&g_din_is[node]);
    float4 o = make_float4(0.f, 0.f, 0.f, 0.f);
    if (act) {
        float4 bv = __ldg(((const float4*)b3) + lane);
        o.x = fmaf(acc.x, din, bv.x);
        o.y = fmaf(acc.y, din, bv.y);
        o.z = fmaf(acc.z, din, bv.z);
        o.w = fmaf(acc.w, din, bv.w);
    }
    float m = act ? fmaxf(fmaxf(o.x, o.y), fmaxf(o.z, o.w)) : -1e30f;
    #pragma unroll
    for (int off = 16; off; off >>= 1)
        m = fmaxf(m, __shfl_xor_sync(0xffffffffu, m, off));
    float e = act ? (expf(o.x - m) + expf(o.y - m) +
                     expf(o.z - m) + expf(o.w - m)) : 0.f;
    #pragma unroll
    for (int off = 16; off; off >>= 1)
        e += __shfl_xor_sync(0xffffffffu, e, off);
    float lse = m + logf(e);
    if (act) {
        float4 r;
        r.x = o.x - lse; r.y = o.y - lse; r.z = o.z - lse; r.w = o.w - lse;
        *(float4*)(out + (size_t)node * 40 + lane * 4) = r;
    }
}

// ---------------------------------------------------------------------------
extern "C" void kernel_launch(void* const* d_in, const int* in_sizes, int n_in,
                              void* d_out, int out_size)
{
    const float* x   = (const float*)d_in[0];
    const int*   src = (const int*)d_in[1];
    const int*   dst = (const int*)d_in[2];
    const float* W1  = (const float*)d_in[3];
    const float* b1  = (const float*)d_in[4];
    const float* g1  = (const float*)d_in[5];
    const float* be1 = (const float*)d_in[6];
    const float* W2  = (const float*)d_in[7];
    const float* b2  = (const float*)d_in[8];
    const float* g2  = (const float*)d_in[9];
    const float* be2 = (const float*)d_in[10];
    const float* W3  = (const float*)d_in[11];
    const float* b3  = (const float*)d_in[12];

    int N = in_sizes[0] / DD;
    int E = in_sizes[1];
    float* out = (float*)d_out;

    float *bufA, *cs1, *cq1, *cs2, *cq2;
    __half2 *bufB, *bufH, *bufAh;
    __half  *bufW;
    cudaGetSymbolAddress((void**)&bufA, g_bufA);
    cudaGetSymbolAddress((void**)&bufB, g_bufB);
    cudaGetSymbolAddress((void**)&bufH, g_half);
    cudaGetSymbolAddress((void**)&bufAh, g_halfA);
    cudaGetSymbolAddress((void**)&bufW, g_halfW);
    cudaGetSymbolAddress((void**)&cs1, g_colsum1);
    cudaGetSymbolAddress((void**)&cq1, g_colsq1);
    cudaGetSymbolAddress((void**)&cs2, g_colsum2);
    cudaGetSymbolAddress((void**)&cq2, g_colsq2);

    cudaFuncSetAttribute(gemm128_mma_kernel,
                         cudaFuncAttributeMaxDynamicSharedMemorySize, SMEM128);
    cudaFuncSetAttribute(gemm40pre_kernel,
                         cudaFuncAttributeMaxDynamicSharedMemorySize, SMEM40);

    int egrid  = (E + 255) / 256;
    int pgrid  = (N + 7) / 8;          // 8 warps (nodes) per 256-thread block
    int qgrid  = (N * 32 + 255) / 256; // prep: one thread per 4 features
    int wgrid  = (2 * DD * DD + 255) / 256;  // W fp16 conversion blocks
    int ggrid  = (N + 63) / 64;
    int chunk  = (N + CHUNKS - 1) / CHUNKS;
    float invN = 1.0f / (float)N;

    // 1-4: degrees + CSR offsets (deg arrays arrive zeroed)
    deg_count_kernel<<<egrid, 256>>>(src, dst, E);
    chunk_sum_kernel<<<CHUNKS / 8, 256>>>(N, chunk);
    scan_chunks_kernel<<<1, 1024>>>(N);
    fill_off_kernel<<<CHUNKS / 8, 256>>>(N, chunk);

    // 5: CSR fill + layer-1 prep + W1/W2 fp16 conversion (one launch)
    csrfill_prep_kernel<<<qgrid + egrid + wgrid, 256>>>(
        src, dst, E, (const float4*)x, bufH, N, qgrid, W1, W2);

    // 6-7: layer 1
    prop_fp16_kernel<<<pgrid, 256>>>((const uint2*)bufH, bufAh, N);
    gemm128_mma_kernel<<<ggrid, 256, SMEM128>>>(
        (const __half*)bufAh, bufW, b1, bufB, N, cs1, cq1);

    // 8-10: layer 2
    prep_bn_kernel<<<qgrid, 256>>>((const uint2*)bufB, bufH, N,
                                   cs1, cq1, g1, be1, invN);
    prop_fp16_kernel<<<pgrid, 256>>>((const uint2*)bufH, bufAh, N);
    gemm128_mma_kernel<<<ggrid, 256, SMEM128>>>(
        (const __half*)bufAh, bufW + DD * DD, b2, bufB, N, cs2, cq2);

    // 11-12: layer 3 (GEMM first — prop and @W3 commute), then 40-wide prop
    gemm40pre_kernel<<<ggrid, 256, SMEM40>>>((const uint2*)bufB, W3,
                                             (__half2*)bufA, N,
                                             cs2, cq2, g2, be2, invN);
    prop40_kernel<<<pgrid, 256>>>((const uint2*)bufA, b3, out, N);
}

// round 17
// speedup vs baseline: 1.2184x; 1.0097x over previous
#include <cuda_runtime.h>
#include <cuda_fp16.h>
#include <mma.h>

using namespace nvcuda;

// ---------------------------------------------------------------------------
// GCN: 3x (GraphConv norm='both') with BN+ReLU between, log_softmax at end.
// N=100000 nodes, E=1.6M edges, D=128, C=40.
//
// Round-17 = R16 with:
//   - gemm128 smem overlay: sOut (32KB f32) aliases sW (32KB fp16) after the
//     k-loop (extra __syncthreads). smem 81KB -> 49KB -> 4 blocks/SM (was 2),
//     doubling warps hiding the L2 staging latency.
//   - deg_count / csr_fill vectorized: int4 loads, 4 edges per thread.
// ---------------------------------------------------------------------------

#define NMAX 100096
#define EMAX 1600000
#define DD 128
#define CHUNKS 1024

__device__ float   g_bufA[(size_t)NMAX * DD];   // 40-wide t buffer (fp16)
__device__ __half2 g_bufB[(size_t)NMAX * 64];   // gemm fp16 output
__device__ __half2 g_half[(size_t)NMAX * 64];   // fp16 gather copy (prop input)
__device__ __half2 g_halfA[(size_t)NMAX * 64];  // fp16 prop output (gemm A)
__device__ __half  g_halfW[2 * DD * DD];        // fp16 W1 | W2
__device__ float   g_dout_is[NMAX];
__device__ float   g_din_is[NMAX];
__device__ int     g_deg_out[NMAX];   // zero on entry (module init / prop40 tail)
__device__ int     g_deg_in[NMAX];    // zero on entry
__device__ int     g_row_off[NMAX + 1];
__device__ int     g_cursor[NMAX];
__device__ int     g_csr_src[EMAX];
__device__ int     g_chunk_sum[CHUNKS];
__device__ float   g_colsum1[DD];     // zero on entry; re-zeroed in prop40
__device__ float   g_colsq1[DD];
__device__ float   g_colsum2[DD];
__device__ float   g_colsq2[DD];

// packed f32x2 helpers (sm_100+: lowers to FFMA2 / 64-bit regs)
#define FMA_F32X2(d, a, b, c) \
    asm("fma.rn.f32x2 %0, %1, %2, %3;" \
        : "=l"(d) : "l"(a), "l"(b), "l"(c))
#define PACKF2(out, lo, hi) \
    asm("mov.b64 %0, {%1, %2};" \
        : "=l"(out) : "r"(__float_as_uint(lo)), "r"(__float_as_uint(hi)))
#define UNPACKF2(lo, hi, in) \
    do { unsigned int _ulo, _uhi; \
         asm("mov.b64 {%0, %1}, %2;" : "=r"(_ulo), "=r"(_uhi) : "l"(in)); \
         lo = __uint_as_float(_ulo); hi = __uint_as_float(_uhi); } while (0)

// ---------------------------------------------------------------------------
// Degree count, 4 edges per thread via int4 loads (atomics unchanged).
// ---------------------------------------------------------------------------
__global__ void deg_count_kernel(const int* __restrict__ src,
                                 const int* __restrict__ dst, int E) {
    int i = blockIdx.x * blockDim.x + threadIdx.x;
    int base = i * 4;
    if (base + 3 < E) {
        int4 s = __ldg((const int4*)(src + base));
        int4 d = __ldg((const int4*)(dst + base));
        atomicAdd(&g_deg_out[s.x], 1); atomicAdd(&g_deg_in[d.x], 1);
        atomicAdd(&g_deg_out[s.y], 1); atomicAdd(&g_deg_in[d.y], 1);
        atomicAdd(&g_deg_out[s.z], 1); atomicAdd(&g_deg_in[d.z], 1);
        atomicAdd(&g_deg_out[s.w], 1); atomicAdd(&g_deg_in[d.w], 1);
    } else {
        for (int k = base; k < E; k++) {
            atomicAdd(&g_deg_out[__ldg(src + k)], 1);
            atomicAdd(&g_deg_in[__ldg(dst + k)], 1);
        }
    }
}

// ---------------------------------------------------------------------------
// Parallel exclusive scan of deg_in -> row_off (3 phases, full-chip).
// ---------------------------------------------------------------------------
__global__ void __launch_bounds__(256) chunk_sum_kernel(int N, int chunk) {
    int w = blockIdx.x * 8 + (threadIdx.x >> 5);
    if (w >= CHUNKS) return;
    int lane = threadIdx.x & 31;
    int lo = w * chunk, hi = min(lo + chunk, N);
    int s = 0;
    for (int i = lo + lane; i < hi; i += 32) s += g_deg_in[i];
    #pragma unroll
    for (int off = 16; off; off >>= 1)
        s += __shfl_down_sync(0xffffffffu, s, off);
    if (lane == 0) g_chunk_sum[w] = s;
}

__global__ void __launch_bounds__(1024) scan_chunks_kernel(int N) {
    __shared__ int sdata[1024];
    int t = threadIdx.x;
    int v = g_chunk_sum[t];
    sdata[t] = v;
    __syncthreads();
    #pragma unroll
    for (int off = 1; off < 1024; off <<= 1) {
        int u = (t >= off) ? sdata[t - off] : 0;
        __syncthreads();
        sdata[t] += u;
        __syncthreads();
    }
    g_chunk_sum[t] = sdata[t] - v;          // exclusive prefix per chunk
    if (t == 1023) g_row_off[N] = sdata[1023];
}

// fill_off + deg_inv folded: writes row_off/cursor AND deg^-1/2 arrays.
__global__ void __launch_bounds__(256) fill_off_kernel(int N, int chunk) {
    int w = blockIdx.x * 8 + (threadIdx.x >> 5);
    if (w >= CHUNKS) return;
    int lane = threadIdx.x & 31;
    int lo = w * chunk, hi = min(lo + chunk, N);
    int run = g_chunk_sum[w];
    for (int base = lo; base < hi; base += 32) {
        int i = base + lane;
        int v = 0;
        if (i < hi) {
            v = __ldg(&g_deg_in[i]);
            int dov = __ldg(&g_deg_out[i]);
            g_din_is[i]  = rsqrtf(fmaxf((float)v, 1.f));
            g_dout_is[i] = rsqrtf(fmaxf((float)dov, 1.f));
        }
        int incl = v;
        #pragma unroll
        for (int off = 1; off < 32; off <<= 1) {
            int t = __shfl_up_sync(0xffffffffu, incl, off);
            if (lane >= off) incl += t;
        }
        if (i < hi) {
            int off_i = run + incl - v;
            g_row_off[i] = off_i;
            g_cursor[i]  = off_i;
        }
        run += __shfl_sync(0xffffffffu, incl, 31);
    }
}

// ---------------------------------------------------------------------------
// Fused launch: blocks [0, qgrid): layer-1 prep (x * dout -> fp16 rows);
// [qgrid, qgrid+e4grid): CSR fill (4 edges/thread); rest: W1|W2 fp32->fp16.
// ---------------------------------------------------------------------------
__global__ void __launch_bounds__(256) csrfill_prep_kernel(
    const int* __restrict__ src, const int* __restrict__ dst, int E,
    const float4* __restrict__ x, __half2* __restrict__ outh, int N,
    int qgrid, int e4grid,
    const float* __restrict__ W1, const float* __restrict__ W2)
{
    int b = (int)blockIdx.x;
    if (b < qgrid) {
        int i = b * 256 + threadIdx.x;
        if (i < N * 32) {
            int node = i >> 5;
            float4 v = __ldg(x + i);
            float sc = __ldg(&g_dout_is[node]);
            outh[i * 2 + 0] = __floats2half2_rn(v.x * sc, v.y * sc);
            outh[i * 2 + 1] = __floats2half2_rn(v.z * sc, v.w * sc);
        }
    } else if (b < qgrid + e4grid) {
        int i = (b - qgrid) * 256 + threadIdx.x;
        int base = i * 4;
        if (base + 3 < E) {
            int4 s = __ldg((const int4*)(src + base));
            int4 d = __ldg((const int4*)(dst + base));
            g_csr_src[atomicAdd(&g_cursor[d.x], 1)] = s.x;
            g_csr_src[atomicAdd(&g_cursor[d.y], 1)] = s.y;
            g_csr_src[atomicAdd(&g_cursor[d.z], 1)] = s.z;
            g_csr_src[atomicAdd(&g_cursor[d.w], 1)] = s.w;
        } else {
            for (int k = base; k < E; k++) {
                int pos = atomicAdd(&g_cursor[__ldg(dst + k)], 1);
                g_csr_src[pos] = __ldg(src + k);
            }
        }
    } else {
        int i = (b - qgrid - e4grid) * 256 + threadIdx.x;
        if (i < 2 * DD * DD) {
            float w = (i < DD * DD) ? __ldg(W1 + i) : __ldg(W2 + i - DD * DD);
            g_halfW[i] = __float2half_rn(w);
        }
    }
}

// ---------------------------------------------------------------------------
// Layer-2 prep with inline BN: per-block compute of the 128 BN coefficients
// (from colsum/colsq stats) into smem, then BN+ReLU+dout scale -> fp16 rows.
// Input is the fp16 gemm output (bufB).
// ---------------------------------------------------------------------------
__global__ void __launch_bounds__(256) prep_bn_kernel(
    const uint2* __restrict__ inh, __half2* __restrict__ outh, int N,
    const float* __restrict__ colsum, const float* __restrict__ colsq,
    const float* __restrict__ g, const float* __restrict__ be, float invN)
{
    __shared__ float sA[128], sB[128];
    int tid = threadIdx.x;
    if (tid < 128) {
        float mu  = __ldg(colsum + tid) * invN;
        float var = fmaf(-mu, mu, __ldg(colsq + tid) * invN);
        float a   = __ldg(g + tid) * rsqrtf(var + 1e-5f);
        sA[tid] = a;
        sB[tid] = fmaf(-mu, a, __ldg(be + tid));
    }
    __syncthreads();

    int i = blockIdx.x * 256 + tid;
    if (i >= N * 32) return;
    int node = i >> 5;
    int q    = i & 31;
    uint2 hv = __ldg(inh + i);
    float2 v01 = __half22float2(*(const __half2*)&hv.x);
    float2 v23 = __half22float2(*(const __half2*)&hv.y);
    float4 a = *(const float4*)(sA + q * 4);
    float4 b = *(const float4*)(sB + q * 4);
    float ox = fmaxf(fmaf(v01.x, a.x, b.x), 0.f);
    float oy = fmaxf(fmaf(v01.y, a.y, b.y), 0.f);
    float oz = fmaxf(fmaf(v23.x, a.z, b.z), 0.f);
    float ow = fmaxf(fmaf(v23.y, a.w, b.w), 0.f);
    float sc = __ldg(&g_dout_is[node]);
    outh[i * 2 + 0] = __floats2half2_rn(ox * sc, oy * sc);
    outh[i * 2 + 1] = __floats2half2_rn(oz * sc, ow * sc);
}

// ---------------------------------------------------------------------------
// fp16 CSR propagation: one warp per dst node. Lane l owns features
// [4l, 4l+4). fp32 accumulation, MLP-4. Output written as fp16 (gemm A).
// ---------------------------------------------------------------------------
__global__ void __launch_bounds__(256) prop_fp16_kernel(
    const uint2* __restrict__ inh, __half2* __restrict__ outh, int N)
{
    int node = blockIdx.x * 8 + (threadIdx.x >> 5);
    if (node >= N) return;
    int lane = threadIdx.x & 31;
    int start = __ldg(&g_row_off[node]);
    int end   = __ldg(&g_row_off[node + 1]);

    float4 acc = make_float4(0.f, 0.f, 0.f, 0.f);
    for (int base = start; base < end; base += 32) {
        int n = min(32, end - base);
        int s = 0;
        if (lane < n) s = __ldg(g_csr_src + base + lane);
        int j = 0;
        for (; j + 4 <= n; j += 4) {
            int s0 = __shfl_sync(0xffffffffu, s, j);
            int s1 = __shfl_sync(0xffffffffu, s, j + 1);
            int s2 = __shfl_sync(0xffffffffu, s, j + 2);
            int s3 = __shfl_sync(0xffffffffu, s, j + 3);
            uint2 r0 = __ldg(inh + (size_t)s0 * 32 + lane);
            uint2 r1 = __ldg(inh + (size_t)s1 * 32 + lane);
            uint2 r2 = __ldg(inh + (size_t)s2 * 32 + lane);
            uint2 r3 = __ldg(inh + (size_t)s3 * 32 + lane);
            float2 a0 = __half22float2(*(const __half2*)&r0.x);
            float2 b0 = __half22float2(*(const __half2*)&r0.y);
            float2 a1 = __half22float2(*(const __half2*)&r1.x);
            float2 b1 = __half22float2(*(const __half2*)&r1.y);
            float2 a2 = __half22float2(*(const __half2*)&r2.x);
            float2 b2 = __half22float2(*(const __half2*)&r2.y);
            float2 a3 = __half22float2(*(const __half2*)&r3.x);
            float2 b3 = __half22float2(*(const __half2*)&r3.y);
            acc.x += (a0.x + a1.x) + (a2.x + a3.x);
            acc.y += (a0.y + a1.y) + (a2.y + a3.y);
            acc.z += (b0.x + b1.x) + (b2.x + b3.x);
            acc.w += (b0.y + b1.y) + (b2.y + b3.y);
        }
        for (; j < n; j++) {
            int sj = __shfl_sync(0xffffffffu, s, j);
            uint2 r = __ldg(inh + (size_t)sj * 32 + lane);
            float2 a = __half22float2(*(const __half2*)&r.x);
            float2 b = __half22float2(*(const __half2*)&r.y);
            acc.x += a.x; acc.y += a.y; acc.z += b.x; acc.w += b.y;
        }
    }
    outh[(size_t)node * 64 + lane * 2 + 0] = __floats2half2_rn(acc.x, acc.y);
    outh[(size_t)node * 64 + lane * 2 + 1] = __floats2half2_rn(acc.z, acc.w);
}

// ---------------------------------------------------------------------------
// Tensor-core GEMM (wmma fp16 -> f32 accum), smem-overlaid:
// sOut (64x128 f32, 32KB) ALIASES sW (128x128 half, 32KB) — sW is dead after
// the k-loop, so one extra sync lets the accumulator staging reuse it.
// smem 49.25KB -> 4 blocks/SM (was 2 at 81KB): 2x warps hiding L2 staging.
// ---------------------------------------------------------------------------
#define SMEM128 (128 * 128 * 2 + 64 * 128 * 2 + 256 * 4)

__global__ void __launch_bounds__(256) gemm128_mma_kernel(
    const __half* __restrict__ Ah, const __half* __restrict__ Wh,
    const float* __restrict__ bias, __half2* __restrict__ outh, int N,
    float* __restrict__ colsum, float* __restrict__ colsq)
{
    extern __shared__ float sm[];
    __half* sW   = (__half*)sm;                     // 128*128 half (32KB)
    float*  sOut = sm;                              // ALIAS: used after k-loop
    __half* sA   = sW + 128 * 128;                  // 64*128 half (16KB)
    float*  sSum = (float*)(sA + 64 * 128);         // [128]
    float*  sSq  = sSum + 128;                      // [128]
    int tid  = threadIdx.x;
    int row0 = blockIdx.x * 64;

    if (tid < 128) { sSum[tid] = 0.f; sSq[tid] = 0.f; }

    // stage W (2048 uint4) and A (1024 uint4, zero-padded past N)
    {
        const uint4* W4 = (const uint4*)Wh;
        uint4* sW4 = (uint4*)sW;
        #pragma unroll
        for (int ii = 0; ii < 8; ii++)
            sW4[tid + ii * 256] = __ldg(W4 + tid + ii * 256);
        uint4* sA4 = (uint4*)sA;
        #pragma unroll
        for (int ii = 0; ii < 4; ii++) {
            int i = tid + ii * 256;          // uint4 index; 16/row
            int r = i >> 4, q = i & 15;
            int rr = row0 + r;
            uint4 v = make_uint4(0u, 0u, 0u, 0u);
            if (rr < N) v = __ldg((const uint4*)(Ah + (size_t)rr * 128) + q);
            sA4[i] = v;
        }
    }
    __syncthreads();

    // warp w: rows m0 = (w&3)*16, cols n0 = (w>>2)*64
    int w  = tid >> 5;
    int m0 = (w & 3) * 16;
    int n0 = (w >> 2) * 64;

    wmma::fragment<wmma::accumulator, 16, 16, 16, float> c[4];
    #pragma unroll
    for (int j = 0; j < 4; j++) wmma::fill_fragment(c[j], 0.f);

    #pragma unroll
    for (int k = 0; k < 128; k += 16) {
        wmma::fragment<wmma::matrix_a, 16, 16, 16, __half, wmma::row_major> a;
        wmma::load_matrix_sync(a, sA + m0 * 128 + k, 128);
        #pragma unroll
        for (int j = 0; j < 4; j++) {
            wmma::fragment<wmma::matrix_b, 16, 16, 16, __half, wmma::row_major> b;
            wmma::load_matrix_sync(b, sW + k * 128 + n0 + j * 16, 128);
            wmma::mma_sync(c[j], a, b, c[j]);
        }
    }
    __syncthreads();   // all sW reads done -> safe to overwrite via sOut alias

    #pragma unroll
    for (int j = 0; j < 4; j++)
        wmma::store_matrix_sync(sOut + m0 * 128 + n0 + j * 16, c[j], 128,
                                wmma::mem_row_major);
    __syncthreads();

    // epilogue: din scale + bias + BN stats (fp32) + fp16 store
    float csum[4] = {0.f, 0.f, 0.f, 0.f};
    float csq[4]  = {0.f, 0.f, 0.f, 0.f};
    int cq = tid & 31;                 // float4 col group (fixed per thread)
    float4 bv = __ldg((const float4*)bias + cq);
    #pragma unroll
    for (int ii = 0; ii < 8; ii++) {
        int r  = (tid >> 5) + ii * 8;  // 8 rows per thread, stride 8
        int rr = row0 + r;
        if (rr < N) {
            float4 v = *((const float4*)(sOut + r * 128) + cq);
            float sc = __ldg(&g_din_is[rr]);
            float4 o;
            o.x = fmaf(v.x, sc, bv.x);
            o.y = fmaf(v.y, sc, bv.y);
            o.z = fmaf(v.z, sc, bv.z);
            o.w = fmaf(v.w, sc, bv.w);
            csum[0] += o.x; csq[0] = fmaf(o.x, o.x, csq[0]);
            csum[1] += o.y; csq[1] = fmaf(o.y, o.y, csq[1]);
            csum[2] += o.z; csq[2] = fmaf(o.z, o.z, csq[2]);
            csum[3] += o.w; csq[3] = fmaf(o.w, o.w, csq[3]);
            __half2* op = outh + (size_t)rr * 64 + cq * 2;
            op[0] = __floats2half2_rn(o.x, o.y);
            op[1] = __floats2half2_rn(o.z, o.w);
        }
    }
    #pragma unroll
    for (int j = 0; j < 4; j++) {
        atomicAdd(&sSum[cq * 4 + j], csum[j]);
        atomicAdd(&sSq[cq * 4 + j],  csq[j]);
    }
    __syncthreads();
    if (tid < 128) {
        atomicAdd(&colsum[tid], sSum[tid]);
        atomicAdd(&colsq[tid],  sSq[tid]);
    }
}

// ---------------------------------------------------------------------------
// Layer-3 pre-prop GEMM: t[r, 0..39] = dout_is[r] * (relu(bn(A[r,:])) @ W3).
// A is fp16 (bufB). BN coefficients per-block in smem. fp16 t output.
// ---------------------------------------------------------------------------
#define SMEM40 ((128 * 64 + 128 * 68) * 4)

__global__ void __launch_bounds__(256) gemm40pre_kernel(
    const uint2* __restrict__ Ah, const float* __restrict__ W3,
    __half2* __restrict__ t, int N,
    const float* __restrict__ colsum, const float* __restrict__ colsq,
    const float* __restrict__ g, const float* __restrict__ be, float invN)
{
    extern __shared__ float sm[];
    float* sW   = sm;                       // [k][c] padded to 64 cols
    float* sAT  = sm + 128 * 64;            // [k][r] ld 68
    __shared__ float sA[128], sB[128];
    int tid  = threadIdx.x;
    int row0 = blockIdx.x * 64;

    if (tid < 128) {
        float mu  = __ldg(colsum + tid) * invN;
        float var = fmaf(-mu, mu, __ldg(colsq + tid) * invN);
        float a   = __ldg(g + tid) * rsqrtf(var + 1e-5f);
        sA[tid] = a;
        sB[tid] = fmaf(-mu, a, __ldg(be + tid));
    }
    for (int i = tid; i < 128 * 64; i += 256) sW[i] = 0.f;
    __syncthreads();
    for (int i = tid; i < 128 * 40; i += 256) {
        int k = i / 40, c = i - k * 40;
        sW[k * 64 + c] = __ldg(W3 + i);
    }
    #pragma unroll
    for (int ii = 0; ii < 8; ii++) {
        int i  = tid + ii * 256;
        int r  = i >> 5;
        int k4 = (i & 31) << 2;
        int rr = row0 + r;
        float2 v01 = make_float2(0.f, 0.f), v23 = make_float2(0.f, 0.f);
        if (rr < N) {
            uint2 hv = __ldg(Ah + (size_t)rr * 32 + (k4 >> 2));
            v01 = __half22float2(*(const __half2*)&hv.x);
            v23 = __half22float2(*(const __half2*)&hv.y);
        }
        float4 a = *(const float4*)(sA + k4);
        float4 b = *(const float4*)(sB + k4);
        sAT[(k4 + 0) * 68 + r] = fmaxf(fmaf(v01.x, a.x, b.x), 0.f);
        sAT[(k4 + 1) * 68 + r] = fmaxf(fmaf(v01.y, a.y, b.y), 0.f);
        sAT[(k4 + 2) * 68 + r] = fmaxf(fmaf(v23.x, a.z, b.z), 0.f);
        sAT[(k4 + 3) * 68 + r] = fmaxf(fmaf(v23.y, a.w, b.w), 0.f);
    }
    __syncthreads();

    int cg = (tid & 15) << 2;   // cols [cg, cg+4) of 64 (only <40 real)
    int rg = (tid >> 4) << 2;   // rows [rg, rg+4)

    unsigned long long accp[2][4];   // row pairs (rg,rg+1),(rg+2,rg+3)
    #pragma unroll
    for (int pr = 0; pr < 2; pr++)
        #pragma unroll
        for (int j = 0; j < 4; j++) accp[pr][j] = 0ull;

    #pragma unroll 8
    for (int k = 0; k < 128; k++) {
        float4 wv = *(const float4*)(sW + k * 64 + cg);
        ulonglong2 a01 = *(const ulonglong2*)(sAT + k * 68 + rg);
        unsigned long long ap[2] = {a01.x, a01.y};
        unsigned long long wd[4];
        PACKF2(wd[0], wv.x, wv.x);
        PACKF2(wd[1], wv.y, wv.y);
        PACKF2(wd[2], wv.z, wv.z);
        PACKF2(wd[3], wv.w, wv.w);
        #pragma unroll
        for (int pr = 0; pr < 2; pr++)
            #pragma unroll
            for (int j = 0; j < 4; j++)
                FMA_F32X2(accp[pr][j], ap[pr], wd[j], accp[pr][j]);
    }

    float acc[4][4];
    #pragma unroll
    for (int pr = 0; pr < 2; pr++)
        #pragma unroll
        for (int j = 0; j < 4; j++) {
            float lo, hi;
            UNPACKF2(lo, hi, accp[pr][j]);
            acc[2 * pr + 0][j] = lo;
            acc[2 * pr + 1][j] = hi;
        }

    if (cg < 40) {
        #pragma unroll
        for (int i = 0; i < 4; i++) {
            int rr = row0 + rg + i;
            if (rr < N) {
                float sc = __ldg(&g_dout_is[rr]);
                __half2* tp = t + (size_t)rr * 20 + (cg >> 1);
                tp[0] = __floats2half2_rn(acc[i][0] * sc, acc[i][1] * sc);
                tp[1] = __floats2half2_rn(acc[i][2] * sc, acc[i][3] * sc);
            }
        }
    }
}

// ---------------------------------------------------------------------------
// 40-wide fp16 CSR propagation + bias + log_softmax. One warp per dst node.
// Lanes 0..9 own 4 features each (uint2 = 2x half2). fp32 accumulation.
// Tail duty: re-zero scratch (deg counters + BN stats) for the next call.
// ---------------------------------------------------------------------------
__global__ void __launch_bounds__(256) prop40_kernel(
    const uint2* __restrict__ t, const float* __restrict__ b3,
    float* __restrict__ out, int N)
{
    int gid = blockIdx.x * 256 + threadIdx.x;
    if (gid < N) { g_deg_out[gid] = 0; g_deg_in[gid] = 0; }
    if (gid < 128) {
        g_colsum1[gid] = 0.f; g_colsq1[gid] = 0.f;
        g_colsum2[gid] = 0.f; g_colsq2[gid] = 0.f;
    }

    int node = blockIdx.x * 8 + (threadIdx.x >> 5);
    if (node >= N) return;
    int lane = threadIdx.x & 31;
    bool act = lane < 10;
    int start = __ldg(&g_row_off[node]);
    int end   = __ldg(&g_row_off[node + 1]);

    float4 acc = make_float4(0.f, 0.f, 0.f, 0.f);
    for (int base = start; base < end; base += 32) {
        int n = min(32, end - base);
        int s = 0;
        if (lane < n) s = __ldg(g_csr_src + base + lane);
        int j = 0;
        for (; j + 4 <= n; j += 4) {
            int s0 = __shfl_sync(0xffffffffu, s, j);
            int s1 = __shfl_sync(0xffffffffu, s, j + 1);
            int s2 = __shfl_sync(0xffffffffu, s, j + 2);
            int s3 = __shfl_sync(0xffffffffu, s, j + 3);
            if (act) {
                uint2 r0 = __ldg(t + (size_t)s0 * 10 + lane);
                uint2 r1 = __ldg(t + (size_t)s1 * 10 + lane);
                uint2 r2 = __ldg(t + (size_t)s2 * 10 + lane);
                uint2 r3 = __ldg(t + (size_t)s3 * 10 + lane);
                float2 a0 = __half22float2(*(const __half2*)&r0.x);
                float2 b0 = __half22float2(*(const __half2*)&r0.y);
                float2 a1 = __half22float2(*(const __half2*)&r1.x);
                float2 b1 = __half22float2(*(const __half2*)&r1.y);
                float2 a2 = __half22float2(*(const __half2*)&r2.x);
                float2 b2 = __half22float2(*(const __half2*)&r2.y);
                float2 a3 = __half22float2(*(const __half2*)&r3.x);
                float2 b3 = __half22float2(*(const __half2*)&r3.y);
                acc.x += (a0.x + a1.x) + (a2.x + a3.x);
                acc.y += (a0.y + a1.y) + (a2.y + a3.y);
                acc.z += (b0.x + b1.x) + (b2.x + b3.x);
                acc.w += (b0.y + b1.y) + (b2.y + b3.y);
            }
        }
        for (; j < n; j++) {
            int sj = __shfl_sync(0xffffffffu, s, j);
            if (act) {
                uint2 r = __ldg(t + (size_t)sj * 10 + lane);
                float2 a = __half22float2(*(const __half2*)&r.x);
                float2 b = __half22float2(*(const __half2*)&r.y);
                acc.x += a.x; acc.y += a.y; acc.z += b.x; acc.w += b.y;
            }
        }
    }

    float din = __ldg(&g_din_is[node]);
    float4 o = make_float4(0.f, 0.f, 0.f, 0.f);
    if (act) {
        float4 bv = __ldg(((const float4*)b3) + lane);
        o.x = fmaf(acc.x, din, bv.x);
        o.y = fmaf(acc.y, din, bv.y);
        o.z = fmaf(acc.z, din, bv.z);
        o.w = fmaf(acc.w, din, bv.w);
    }
    float m = act ? fmaxf(fmaxf(o.x, o.y), fmaxf(o.z, o.w)) : -1e30f;
    #pragma unroll
    for (int off = 16; off; off >>= 1)
        m = fmaxf(m, __shfl_xor_sync(0xffffffffu, m, off));
    float e = act ? (expf(o.x - m) + expf(o.y - m) +
                     expf(o.z - m) + expf(o.w - m)) : 0.f;
    #pragma unroll
    for (int off = 16; off; off >>= 1)
        e += __shfl_xor_sync(0xffffffffu, e, off);
    float lse = m + logf(e);
    if (act) {
        float4 r;
        r.x = o.x - lse; r.y = o.y - lse; r.z = o.z - lse; r.w = o.w - lse;
        *(float4*)(out + (size_t)node * 40 + lane * 4) = r;
    }
}

// ---------------------------------------------------------------------------
extern "C" void kernel_launch(void* const* d_in, const int* in_sizes, int n_in,
                              void* d_out, int out_size)
{
    const float* x   = (const float*)d_in[0];
    const int*   src = (const int*)d_in[1];
    const int*   dst = (const int*)d_in[2];
    const float* W1  = (const float*)d_in[3];
    const float* b1  = (const float*)d_in[4];
    const float* g1  = (const float*)d_in[5];
    const float* be1 = (const float*)d_in[6];
    const float* W2  = (const float*)d_in[7];
    const float* b2  = (const float*)d_in[8];
    const float* g2  = (const float*)d_in[9];
    const float* be2 = (const float*)d_in[10];
    const float* W3  = (const float*)d_in[11];
    const float* b3  = (const float*)d_in[12];

    int N = in_sizes[0] / DD;
    int E = in_sizes[1];
    float* out = (float*)d_out;

    float *bufA, *cs1, *cq1, *cs2, *cq2;
    __half2 *bufB, *bufH, *bufAh;
    __half  *bufW;
    cudaGetSymbolAddress((void**)&bufA, g_bufA);
    cudaGetSymbolAddress((void**)&bufB, g_bufB);
    cudaGetSymbolAddress((void**)&bufH, g_half);
    cudaGetSymbolAddress((void**)&bufAh, g_halfA);
    cudaGetSymbolAddress((void**)&bufW, g_halfW);
    cudaGetSymbolAddress((void**)&cs1, g_colsum1);
    cudaGetSymbolAddress((void**)&cq1, g_colsq1);
    cudaGetSymbolAddress((void**)&cs2, g_colsum2);
    cudaGetSymbolAddress((void**)&cq2, g_colsq2);

    cudaFuncSetAttribute(gemm128_mma_kernel,
                         cudaFuncAttributeMaxDynamicSharedMemorySize, SMEM128);
    cudaFuncSetAttribute(gemm40pre_kernel,
                         cudaFuncAttributeMaxDynamicSharedMemorySize, SMEM40);

    int e4grid = (E + 1023) / 1024;    // 4 edges per thread
    int pgrid  = (N + 7) / 8;          // 8 warps (nodes) per 256-thread block
    int qgrid  = (N * 32 + 255) / 256; // prep: one thread per 4 features
    int wgrid  = (2 * DD * DD + 255) / 256;  // W fp16 conversion blocks
    int ggrid  = (N + 63) / 64;
    int chunk  = (N + CHUNKS - 1) / CHUNKS;
    float invN = 1.0f / (float)N;

    // 1-4: degrees + CSR offsets (deg arrays arrive zeroed)
    deg_count_kernel<<<e4grid, 256>>>(src, dst, E);
    chunk_sum_kernel<<<CHUNKS / 8, 256>>>(N, chunk);
    scan_chunks_kernel<<<1, 1024>>>(N);
    fill_off_kernel<<<CHUNKS / 8, 256>>>(N, chunk);

    // 5: CSR fill (4 edges/thread) + layer-1 prep + W fp16 conv (one launch)
    csrfill_prep_kernel<<<qgrid + e4grid + wgrid, 256>>>(
        src, dst, E, (const float4*)x, bufH, N, qgrid, e4grid, W1, W2);

    // 6-7: layer 1
    prop_fp16_kernel<<<pgrid, 256>>>((const uint2*)bufH, bufAh, N);
    gemm128_mma_kernel<<<ggrid, 256, SMEM128>>>(
        (const __half*)bufAh, bufW, b1, bufB, N, cs1, cq1);

    // 8-10: layer 2
    prep_bn_kernel<<<qgrid, 256>>>((const uint2*)bufB, bufH, N,
                                   cs1, cq1, g1, be1, invN);
    prop_fp16_kernel<<<pgrid, 256>>>((const uint2*)bufH, bufAh, N);
    gemm128_mma_kernel<<<ggrid, 256, SMEM128>>>(
        (const __half*)bufAh, bufW + DD * DD, b2, bufB, N, cs2, cq2);

    // 11-12: layer 3 (GEMM first — prop and @W3 commute), then 40-wide prop
    gemm40pre_kernel<<<ggrid, 256, SMEM40>>>((const uint2*)bufB, W3,
                                             (__half2*)bufA, N,
                                             cs2, cq2, g2, be2, invN);
    prop40_kernel<<<pgrid, 256>>>((const uint2*)bufA, b3, out, N);
}